// round 16
// baseline (speedup 1.0000x reference)
#include <cuda_runtime.h>
#include <cuda_fp16.h>
#include <cstdint>
#include <math.h>

// ---------------- problem dims (fixed) ----------------
#define HID   512
#define EXPD  2048
#define BATCH 4
#define SEQ   4096
#define M_TOT (BATCH*SEQ)      // 16384
#define HM    (M_TOT/2)        // 8192 (batches 0-1 / 2-3)
#define NCH 64
#define CHL 64

// ---------------- scratch (device globals; 16B aligned) ----------------
__device__ __align__(16) __half g_xh  [(size_t)M_TOT*HID];
__device__ __align__(16) __half g_w12 [(size_t)2*EXPD*HID];    // rows 0..2047 = W_in1^T, 2048..4095 = W_in2^T
__device__ __align__(16) __half g_wzh [(size_t)2*EXPD*EXPD];   // interleaved: row 2f=Wz_f, 2f+1=Wh_f
__device__ __align__(16) __half g_woh [(size_t)HID*EXPD];
__device__ __align__(16) __half g_xin [(size_t)M_TOT*EXPD];
__device__ __align__(16) __half g_zht [(size_t)M_TOT*2*EXPD];  // interleaved (z, ht) pairs
__device__ __align__(16) __half g_xskip[(size_t)M_TOT*EXPD];
__device__ __align__(16) __half g_u   [(size_t)M_TOT*EXPD];
__device__ __align__(16) float g_aggA [(size_t)BATCH*NCH*EXPD];
__device__ __align__(16) float g_aggB [(size_t)BATCH*NCH*EXPD];
__device__ __align__(16) float g_carry[(size_t)BATCH*NCH*EXPD];

// ---------------- PTX helpers (base-target features only) ----------------
__device__ __forceinline__ uint32_t smem_u32(const void* p) {
    uint32_t a;
    asm("{ .reg .u64 t; cvta.to.shared.u64 t, %1; cvt.u32.u64 %0, t; }" : "=r"(a) : "l"(p));
    return a;
}
__device__ __forceinline__ void cp16(uint32_t dst, const void* src) {
    asm volatile("cp.async.cg.shared.global [%0], [%1], 16;" :: "r"(dst), "l"(src));
}
#define CP_COMMIT() asm volatile("cp.async.commit_group;" ::: "memory")
#define CP_WAIT(n)  asm volatile("cp.async.wait_group %0;" :: "n"(n) : "memory")

__device__ __forceinline__ void ldsm4(uint32_t* r, uint32_t addr) {
    asm volatile("ldmatrix.sync.aligned.m8n8.x4.shared.b16 {%0,%1,%2,%3}, [%4];"
        : "=r"(r[0]), "=r"(r[1]), "=r"(r[2]), "=r"(r[3]) : "r"(addr));
}
__device__ __forceinline__ void mma_f16(float* c, const uint32_t* a, const uint32_t* b) {
    asm volatile(
        "mma.sync.aligned.m16n8k16.row.col.f32.f16.f16.f32 "
        "{%0,%1,%2,%3}, {%4,%5,%6,%7}, {%8,%9}, {%0,%1,%2,%3};"
        : "+f"(c[0]), "+f"(c[1]), "+f"(c[2]), "+f"(c[3])
        : "r"(a[0]), "r"(a[1]), "r"(a[2]), "r"(a[3]), "r"(b[0]), "r"(b[1]));
}

// ---------------- mma.sync GEMM ----------------
// MODE 0: Cf fp32, no act (out-proj)
// MODE 2: gate-pair — even col v0 -> sigmoid(+bias[f]), odd col v1 -> +bias2[f];
//         packed (z,ht) half2 written as one 32-bit store to Ch (interleaved zht).
// MODE 3: fused in-proj — N=2*EXPD; col<EXPD -> silu(+bias)->Ch[m*EXPD+col],
//         col>=EXPD -> silu(+bias2)->Ch2[m*EXPD+col-EXPD].
#define BM 128
#define BN 128
#define BK 64
#define NTHREADS 256
#define T_A 0
#define T_B 16384
#define STAGE_BYTES 32768
#define NSTAGE 3
#define SMEM_BYTES (NSTAGE*STAGE_BYTES)

template<int MODE>
__global__ __launch_bounds__(NTHREADS, 2)
void gemm_mma(const __half* __restrict__ A, const __half* __restrict__ B,
              const float* __restrict__ bias, const float* __restrict__ bias2,
              float* __restrict__ Cf, __half* __restrict__ Ch, __half* __restrict__ Ch2,
              int M, int N, int K)
{
    extern __shared__ char smem[];
    const uint32_t sb = smem_u32(smem);
    const int tid  = threadIdx.x;
    const int wid  = tid >> 5;
    const int lane = tid & 31;
    const int wm = wid >> 1;           // 0..3  -> m offset wm*32
    const int wn = wid & 1;            // 0..1  -> n offset wn*64
    const int bm = blockIdx.y * BM;
    const int bn = blockIdx.x * BN;

    const int Kv = K >> 3;             // row pitch in uint4 (8 fp16)
    const uint4* gA = (const uint4*)A;
    const uint4* gB = (const uint4*)B;

    const int nk = K / BK;

    auto load_stage = [&](int buf, int kc) {
        const int kv0 = kc * (BK / 8);
        const uint32_t base = sb + buf * STAGE_BYTES;
        #pragma unroll
        for (int t = 0; t < 4; t++) {           // A: 128 rows x 8 chunks
            int i = tid + t * NTHREADS;
            int row = i >> 3, ch = i & 7;
            uint32_t so = (uint32_t)(row * 128 + ((ch ^ (row & 7)) << 4));
            cp16(base + T_A + so, gA + (size_t)(bm + row) * Kv + kv0 + ch);
        }
        #pragma unroll
        for (int t = 0; t < 4; t++) {           // B: 128 rows x 8 chunks
            int i = tid + t * NTHREADS;
            int row = i >> 3, ch = i & 7;
            uint32_t so = (uint32_t)(row * 128 + ((ch ^ (row & 7)) << 4));
            cp16(base + T_B + so, gB + (size_t)(bn + row) * Kv + kv0 + ch);
        }
    };

    float acc[2][8][4];
    #pragma unroll
    for (int mi = 0; mi < 2; mi++)
        #pragma unroll
        for (int ni = 0; ni < 8; ni++)
            #pragma unroll
            for (int q = 0; q < 4; q++)
                acc[mi][ni][q] = 0.f;

    load_stage(0, 0);
    CP_COMMIT();
    load_stage(1, 1);
    CP_COMMIT();

    for (int kc = 0; kc < nk; kc++) {
        const int buf = kc % NSTAGE;
        if (kc + 1 < nk) { CP_WAIT(1); } else { CP_WAIT(0); }
        __syncthreads();
        if (kc + 2 < nk) {
            load_stage((kc + 2) % NSTAGE, kc + 2);
            CP_COMMIT();
        }

        const uint32_t st = sb + buf * STAGE_BYTES;
        #pragma unroll
        for (int kk = 0; kk < BK / 16; kk++) {
            const int byteCol = kk * 32 + ((lane >> 4) << 4);
            uint32_t ah[2][4];
            #pragma unroll
            for (int mi = 0; mi < 2; mi++) {
                int row = wm * 32 + mi * 16 + (lane & 15);
                uint32_t so = (uint32_t)(row * 128 + byteCol) ^ ((uint32_t)(row & 7) << 4);
                ldsm4(ah[mi], st + T_A + so);
            }
            #pragma unroll
            for (int nt = 0; nt < 4; nt++) {
                int row = wn * 64 + nt * 16 + (lane & 15);
                uint32_t so = (uint32_t)(row * 128 + byteCol) ^ ((uint32_t)(row & 7) << 4);
                uint32_t rh[4];
                ldsm4(rh, st + T_B + so);
                uint32_t b0[2] = { rh[0], rh[2] }, b1[2] = { rh[1], rh[3] };
                #pragma unroll
                for (int mi = 0; mi < 2; mi++) {
                    mma_f16(acc[mi][2*nt+0], ah[mi], b0);
                    mma_f16(acc[mi][2*nt+1], ah[mi], b1);
                }
            }
        }
    }

    // ---------------- epilogue ----------------
    const int qrow = lane >> 2;        // 0..7
    const int qcol = (lane & 3) * 2;   // 0,2,4,6 (always even)
    #pragma unroll
    for (int mi = 0; mi < 2; mi++) {
        #pragma unroll
        for (int ni = 0; ni < 8; ni++) {
            const int n0 = bn + wn * 64 + ni * 8 + qcol;
            float bias0, bias1;
            if (MODE == 2) {
                const int f = n0 >> 1;
                bias0 = bias[f];       // b_z
                bias1 = bias2[f];      // b_h
            } else if (MODE == 3) {
                const int f = (n0 < EXPD) ? n0 : n0 - EXPD;
                const float* bp = (n0 < EXPD) ? bias : bias2;
                bias0 = bp[f];
                bias1 = bp[f + 1];
            } else {
                bias0 = bias[n0];
                bias1 = bias[n0 + 1];
            }
            #pragma unroll
            for (int half_ = 0; half_ < 2; half_++) {
                const int m = bm + wm * 32 + mi * 16 + qrow + half_ * 8;
                float v0 = acc[mi][ni][half_ * 2 + 0] + bias0;
                float v1 = acc[mi][ni][half_ * 2 + 1] + bias1;
                if (MODE == 3) {
                    v0 *= 1.f / (1.f + expf(-v0));
                    v1 *= 1.f / (1.f + expf(-v1));
                } else if (MODE == 2) {
                    v0 = 1.f / (1.f + expf(-v0));   // z = sigmoid ; v1 = ht (no act)
                }
                if (MODE == 0) {
                    *(float2*)&Cf[(size_t)m * N + n0] = make_float2(v0, v1);
                } else {
                    __half h0 = __float2half_rn(v0);
                    __half h1 = __float2half_rn(v1);
                    uint32_t hp = (uint32_t)__half_as_ushort(h0) | ((uint32_t)__half_as_ushort(h1) << 16);
                    if (MODE == 3) {
                        __half* dst = (n0 < EXPD) ? Ch : Ch2;
                        const int f = (n0 < EXPD) ? n0 : n0 - EXPD;
                        *(uint32_t*)&dst[(size_t)m * EXPD + f] = hp;
                    } else {
                        *(uint32_t*)&Ch[(size_t)m * N + n0] = hp;
                    }
                }
            }
        }
    }
}

// ---------------- weight transpose: W[K,N] fp32 -> T[(n*mult+off), K] fp16 ----------
__global__ __launch_bounds__(256)
void transpose_h(const float* __restrict__ W, __half* __restrict__ T, int K, int N,
                 int mult, int off)
{
    __shared__ float t[32][33];
    const int n0 = blockIdx.x * 32, k0 = blockIdx.y * 32;
    const int tx = threadIdx.x & 31, ty0 = threadIdx.x >> 5;
    #pragma unroll
    for (int dy = 0; dy < 32; dy += 8)
        t[ty0 + dy][tx] = W[(size_t)(k0 + ty0 + dy) * N + n0 + tx];
    __syncthreads();
    #pragma unroll
    for (int dy = 0; dy < 32; dy += 8) {
        int ty = ty0 + dy;
        T[(size_t)((n0 + ty) * mult + off) * K + k0 + tx] = __float2half_rn(t[tx][ty]);
    }
}

// ---------------- x convert: fp32 -> fp16 ----------------
__global__ __launch_bounds__(256)
void convert_h(const float* __restrict__ x, __half* __restrict__ h, int n)
{
    int i = blockIdx.x * blockDim.x + threadIdx.x;
    if (i < n) h[i] = __float2half_rn(x[i]);
}

// ---------------- scan (minGRU), 3-pass chunked; bb0 = first batch of this launch ------
__global__ __launch_bounds__(256)
void scan_pass1(const __half* __restrict__ zht,
                float* __restrict__ aggA, float* __restrict__ aggB, int bb0)
{
    int t = blockIdx.x * blockDim.x + threadIdx.x;      // over 2 batches
    int f = t % EXPD, rc = t / EXPD, c = rc % NCH, bb = bb0 + rc / NCH;
    size_t base = ((size_t)bb * SEQ + (size_t)c * CHL) * (2 * EXPD) + 2 * f;
    float A = 1.f, B = 0.f;
    #pragma unroll 4
    for (int i = 0; i < CHL; i++) {
        __half2 p = *(const __half2*)(zht + base + (size_t)i * (2 * EXPD));
        float zi = __half2float(__low2half(p)), hi = __half2float(__high2half(p));
        float ai = 1.f - zi, bi = zi * hi;
        A = A * ai;
        B = B * ai + bi;
    }
    size_t tg = (size_t)t + (size_t)bb0 * NCH * EXPD;
    aggA[tg] = A; aggB[tg] = B;
}

__global__ __launch_bounds__(256)
void scan_pass2(const float* __restrict__ aggA, const float* __restrict__ aggB,
                float* __restrict__ carry, int bb0)
{
    int t = blockIdx.x * blockDim.x + threadIdx.x;      // over 2 batches
    int f = t % EXPD, bb = bb0 + t / EXPD;
    size_t base = (size_t)bb * NCH * EXPD + f;
    float h = 0.f;
    for (int c = 0; c < NCH; c++) {
        size_t idx = base + (size_t)c * EXPD;
        carry[idx] = h;
        h = aggA[idx] * h + aggB[idx];
    }
}

__global__ __launch_bounds__(256)
void scan_pass3(const __half* __restrict__ zht,
                const float* __restrict__ carry, const __half* __restrict__ xskip,
                __half* __restrict__ u, int bb0)
{
    int t = blockIdx.x * blockDim.x + threadIdx.x;      // over 2 batches
    int f = t % EXPD, rc = t / EXPD, c = rc % NCH, bb = bb0 + rc / NCH;
    size_t row0 = (size_t)bb * SEQ + (size_t)c * CHL;
    size_t basez = row0 * (2 * EXPD) + 2 * f;
    size_t baseu = row0 * EXPD + f;
    float h = carry[(size_t)t + (size_t)bb0 * NCH * EXPD];
    #pragma unroll 4
    for (int i = 0; i < CHL; i++) {
        __half2 p = *(const __half2*)(zht + basez + (size_t)i * (2 * EXPD));
        float zi = __half2float(__low2half(p)), hti = __half2float(__high2half(p));
        h = (1.f - zi) * h + zi * hti;
        size_t iu = baseu + (size_t)i * EXPD;
        u[iu] = __float2half_rn(__half2float(xskip[iu]) + h);
    }
}

// ---------------- launch (chunked, stream-overlapped DAG; graph-capturable) ------------
extern "C" void kernel_launch(void* const* d_in, const int* in_sizes, int n_in,
                              void* d_out, int out_size)
{
    const float* x     = (const float*)d_in[0];
    const float* W_in1 = (const float*)d_in[1];
    const float* b_in1 = (const float*)d_in[2];
    const float* W_in2 = (const float*)d_in[3];
    const float* b_in2 = (const float*)d_in[4];
    const float* W_z   = (const float*)d_in[5];
    const float* b_z   = (const float*)d_in[6];
    const float* W_h   = (const float*)d_in[7];
    const float* b_h   = (const float*)d_in[8];
    const float* W_out = (const float*)d_in[9];
    const float* b_out = (const float*)d_in[10];
    float* out = (float*)d_out;

    __half *xh, *w12, *wzh, *woh, *xin, *zht, *xskip, *u;
    float *aggA, *aggB, *carry;
    cudaGetSymbolAddress((void**)&xh, g_xh);
    cudaGetSymbolAddress((void**)&w12, g_w12);
    cudaGetSymbolAddress((void**)&wzh, g_wzh);   cudaGetSymbolAddress((void**)&woh, g_woh);
    cudaGetSymbolAddress((void**)&xin, g_xin);
    cudaGetSymbolAddress((void**)&zht, g_zht);
    cudaGetSymbolAddress((void**)&xskip, g_xskip);
    cudaGetSymbolAddress((void**)&u, g_u);
    cudaGetSymbolAddress((void**)&aggA, g_aggA); cudaGetSymbolAddress((void**)&aggB, g_aggB);
    cudaGetSymbolAddress((void**)&carry, g_carry);

    cudaFuncSetAttribute(gemm_mma<0>, cudaFuncAttributeMaxDynamicSharedMemorySize, SMEM_BYTES);
    cudaFuncSetAttribute(gemm_mma<2>, cudaFuncAttributeMaxDynamicSharedMemorySize, SMEM_BYTES);
    cudaFuncSetAttribute(gemm_mma<3>, cudaFuncAttributeMaxDynamicSharedMemorySize, SMEM_BYTES);

    static cudaStream_t s1 = nullptr, s2 = nullptr;
    static cudaEvent_t ev_root, ev_conv, ev_w12, ev_wzh, ev_ip1, ev_gate0, ev_out0;
    if (!s1) {
        cudaStreamCreateWithFlags(&s1, cudaStreamNonBlocking);
        cudaStreamCreateWithFlags(&s2, cudaStreamNonBlocking);
        cudaEventCreateWithFlags(&ev_root,  cudaEventDisableTiming);
        cudaEventCreateWithFlags(&ev_conv,  cudaEventDisableTiming);
        cudaEventCreateWithFlags(&ev_w12,   cudaEventDisableTiming);
        cudaEventCreateWithFlags(&ev_wzh,   cudaEventDisableTiming);
        cudaEventCreateWithFlags(&ev_ip1,   cudaEventDisableTiming);
        cudaEventCreateWithFlags(&ev_gate0, cudaEventDisableTiming);
        cudaEventCreateWithFlags(&ev_out0,  cudaEventDisableTiming);
    }
    cudaStream_t s0 = 0;   // legacy/capture stream

    cudaEventRecord(ev_root, s0);
    cudaStreamWaitEvent(s1, ev_root, 0);
    cudaStreamWaitEvent(s2, ev_root, 0);

    // s1: W_in1^T and W_in2^T concatenated into w12 (rows 0..2047, 2048..4095)
    transpose_h<<<dim3(EXPD/32, HID/32), 256, 0, s1>>>(W_in1, w12, HID, EXPD, 1, 0);
    transpose_h<<<dim3(EXPD/32, HID/32), 256, 0, s1>>>(W_in2, w12 + (size_t)EXPD * HID,
                                                       HID, EXPD, 1, 0);
    cudaEventRecord(ev_w12, s1);

    // s2: interleaved W_z/W_h transpose, then W_out^T
    transpose_h<<<dim3(EXPD/32, EXPD/32), 256, 0, s2>>>(W_z, wzh, EXPD, EXPD, 2, 0);
    transpose_h<<<dim3(EXPD/32, EXPD/32), 256, 0, s2>>>(W_h, wzh, EXPD, EXPD, 2, 1);
    cudaEventRecord(ev_wzh, s2);
    transpose_h<<<dim3(HID/32, EXPD/32), 256, 0, s2>>>(W_out, woh, EXPD, HID, 1, 0);

    // s0: convert x, fused in-proj half0 (N = 2*EXPD -> xin/xskip)
    convert_h<<<(M_TOT * HID + 255) / 256, 256, 0, s0>>>(x, xh, M_TOT * HID);
    cudaEventRecord(ev_conv, s0);
    cudaStreamWaitEvent(s0, ev_w12, 0);
    gemm_mma<3><<<dim3(2*EXPD/BN, HM/BM), NTHREADS, SMEM_BYTES, s0>>>(
        xh, w12, b_in1, b_in2, nullptr, xin, xskip, HM, 2*EXPD, HID);

    // s1: fused in-proj half1 (needs xh; w12 in-order on s1)
    cudaStreamWaitEvent(s1, ev_conv, 0);
    gemm_mma<3><<<dim3(2*EXPD/BN, HM/BM), NTHREADS, SMEM_BYTES, s1>>>(
        xh + (size_t)HM * HID, w12, b_in1, b_in2, nullptr,
        xin + (size_t)HM * EXPD, xskip + (size_t)HM * EXPD, HM, 2*EXPD, HID);
    cudaEventRecord(ev_ip1, s1);

    // s0: gate half0 (overlaps in-proj half1), then gate half1
    cudaStreamWaitEvent(s0, ev_wzh, 0);
    gemm_mma<2><<<dim3(2*EXPD/BN, HM/BM), NTHREADS, SMEM_BYTES, s0>>>(
        xin, wzh, b_z, b_h, nullptr, zht, nullptr, HM, 2*EXPD, EXPD);
    cudaEventRecord(ev_gate0, s0);
    cudaStreamWaitEvent(s0, ev_ip1, 0);
    gemm_mma<2><<<dim3(2*EXPD/BN, HM/BM), NTHREADS, SMEM_BYTES, s0>>>(
        xin + (size_t)HM * EXPD, wzh, b_z, b_h, nullptr,
        zht + (size_t)HM * 2 * EXPD, nullptr, HM, 2*EXPD, EXPD);

    // s2: scan + out for batches 0-1 (overlaps gate half1 on s0)
    const int p1h = 2 * NCH * EXPD;      // threads per 2 batches
    cudaStreamWaitEvent(s2, ev_gate0, 0);
    scan_pass1<<<p1h / 256, 256, 0, s2>>>(zht, aggA, aggB, 0);
    scan_pass2<<<(2 * EXPD) / 256, 256, 0, s2>>>(aggA, aggB, carry, 0);
    scan_pass3<<<p1h / 256, 256, 0, s2>>>(zht, carry, xskip, u, 0);
    gemm_mma<0><<<dim3(HID/BN, HM/BM), NTHREADS, SMEM_BYTES, s2>>>(
        u, woh, b_out, nullptr, out, nullptr, nullptr, HM, HID, EXPD);
    cudaEventRecord(ev_out0, s2);

    // s0: scan + out for batches 2-3 (out half0 on s2 overlaps this scan)
    scan_pass1<<<p1h / 256, 256, 0, s0>>>(zht, aggA, aggB, 2);
    scan_pass2<<<(2 * EXPD) / 256, 256, 0, s0>>>(aggA, aggB, carry, 2);
    scan_pass3<<<p1h / 256, 256, 0, s0>>>(zht, carry, xskip, u, 2);
    gemm_mma<0><<<dim3(HID/BN, HM/BM), NTHREADS, SMEM_BYTES, s0>>>(
        u + (size_t)HM * EXPD, woh, b_out, nullptr,
        out + (size_t)HM * HID, nullptr, nullptr, HM, HID, EXPD);

    // join side streams back into capture stream
    cudaStreamWaitEvent(s0, ev_out0, 0);
}

// round 17
// speedup vs baseline: 1.0320x; 1.0320x over previous
#include <cuda_runtime.h>
#include <cuda_fp16.h>
#include <cstdint>
#include <math.h>

// ---------------- problem dims (fixed) ----------------
#define HID   512
#define EXPD  2048
#define BATCH 4
#define SEQ   4096
#define M_TOT (BATCH*SEQ)      // 16384
#define HM    (M_TOT/2)        // 8192 (batches 0-1 / 2-3)
#define NCH 64
#define CHL 64

// ---------------- scratch (device globals; 16B aligned) ----------------
__device__ __align__(16) __half g_xh  [(size_t)M_TOT*HID];
__device__ __align__(16) __half g_w1h [(size_t)EXPD*HID];
__device__ __align__(16) __half g_w2h [(size_t)EXPD*HID];
__device__ __align__(16) __half g_wzh [(size_t)2*EXPD*EXPD];   // interleaved: row 2f=Wz_f, 2f+1=Wh_f
__device__ __align__(16) __half g_woh [(size_t)HID*EXPD];
__device__ __align__(16) __half g_xin [(size_t)M_TOT*EXPD];
__device__ __align__(16) __half g_zht [(size_t)M_TOT*2*EXPD];  // interleaved (z, ht) pairs
__device__ __align__(16) __half g_xskip[(size_t)M_TOT*EXPD];
__device__ __align__(16) __half g_u   [(size_t)M_TOT*EXPD];
__device__ __align__(16) float g_aggA [(size_t)BATCH*NCH*EXPD];
__device__ __align__(16) float g_aggB [(size_t)BATCH*NCH*EXPD];
__device__ __align__(16) float g_carry[(size_t)BATCH*NCH*EXPD];

// ---------------- PTX helpers ----------------
__device__ __forceinline__ uint32_t smem_u32(const void* p) {
    uint32_t a;
    asm("{ .reg .u64 t; cvta.to.shared.u64 t, %1; cvt.u32.u64 %0, t; }" : "=r"(a) : "l"(p));
    return a;
}
__device__ __forceinline__ void cp16(uint32_t dst, const void* src) {
    asm volatile("cp.async.cg.shared.global [%0], [%1], 16;" :: "r"(dst), "l"(src));
}
#define CP_COMMIT() asm volatile("cp.async.commit_group;" ::: "memory")
#define CP_WAIT(n)  asm volatile("cp.async.wait_group %0;" :: "n"(n) : "memory")

__device__ __forceinline__ void ldsm4(uint32_t* r, uint32_t addr) {
    asm volatile("ldmatrix.sync.aligned.m8n8.x4.shared.b16 {%0,%1,%2,%3}, [%4];"
        : "=r"(r[0]), "=r"(r[1]), "=r"(r[2]), "=r"(r[3]) : "r"(addr));
}
__device__ __forceinline__ void mma_f16(float* c, const uint32_t* a, const uint32_t* b) {
    asm volatile(
        "mma.sync.aligned.m16n8k16.row.col.f32.f16.f16.f32 "
        "{%0,%1,%2,%3}, {%4,%5,%6,%7}, {%8,%9}, {%0,%1,%2,%3};"
        : "+f"(c[0]), "+f"(c[1]), "+f"(c[2]), "+f"(c[3])
        : "r"(a[0]), "r"(a[1]), "r"(a[2]), "r"(a[3]), "r"(b[0]), "r"(b[1]));
}

// ---------------- mma.sync GEMM ----------------
// MODE 0: Cf fp32, no act (out-proj)
// MODE 1: Ch fp16, silu (in-proj)
// MODE 2: gate-pair — even col v0 -> sigmoid(+bias[f]), odd col v1 -> +bias2[f];
//         packed (z,ht) half2 written as one 32-bit store to Ch (interleaved zht).
#define BM 128
#define BN 128
#define BK 64
#define NTHREADS 256
#define T_A 0
#define T_B 16384
#define STAGE_BYTES 32768
#define NSTAGE 3
#define SMEM_BYTES (NSTAGE*STAGE_BYTES)

template<int MODE>
__global__ __launch_bounds__(NTHREADS, 2)
void gemm_mma(const __half* __restrict__ A, const __half* __restrict__ B,
              const float* __restrict__ bias, const float* __restrict__ bias2,
              float* __restrict__ Cf, __half* __restrict__ Ch,
              int M, int N, int K)
{
    extern __shared__ char smem[];
    const uint32_t sb = smem_u32(smem);
    const int tid  = threadIdx.x;
    const int wid  = tid >> 5;
    const int lane = tid & 31;
    const int wm = wid >> 1;           // 0..3  -> m offset wm*32
    const int wn = wid & 1;            // 0..1  -> n offset wn*64
    const int bm = blockIdx.y * BM;
    const int bn = blockIdx.x * BN;

    const int Kv = K >> 3;             // row pitch in uint4 (8 fp16)
    const uint4* gA = (const uint4*)A;
    const uint4* gB = (const uint4*)B;

    const int nk = K / BK;

    auto load_stage = [&](int buf, int kc) {
        const int kv0 = kc * (BK / 8);
        const uint32_t base = sb + buf * STAGE_BYTES;
        #pragma unroll
        for (int t = 0; t < 4; t++) {           // A: 128 rows x 8 chunks
            int i = tid + t * NTHREADS;
            int row = i >> 3, ch = i & 7;
            uint32_t so = (uint32_t)(row * 128 + ((ch ^ (row & 7)) << 4));
            cp16(base + T_A + so, gA + (size_t)(bm + row) * Kv + kv0 + ch);
        }
        #pragma unroll
        for (int t = 0; t < 4; t++) {           // B: 128 rows x 8 chunks
            int i = tid + t * NTHREADS;
            int row = i >> 3, ch = i & 7;
            uint32_t so = (uint32_t)(row * 128 + ((ch ^ (row & 7)) << 4));
            cp16(base + T_B + so, gB + (size_t)(bn + row) * Kv + kv0 + ch);
        }
    };

    float acc[2][8][4];
    #pragma unroll
    for (int mi = 0; mi < 2; mi++)
        #pragma unroll
        for (int ni = 0; ni < 8; ni++)
            #pragma unroll
            for (int q = 0; q < 4; q++)
                acc[mi][ni][q] = 0.f;

    load_stage(0, 0);
    CP_COMMIT();
    load_stage(1, 1);
    CP_COMMIT();

    int buf = 0, pbuf = 2;
    for (int kc = 0; kc < nk; kc++) {
        if (kc + 1 < nk) { CP_WAIT(1); } else { CP_WAIT(0); }
        __syncthreads();
        if (kc + 2 < nk) {
            load_stage(pbuf, kc + 2);
            CP_COMMIT();
        }

        const uint32_t st = sb + buf * STAGE_BYTES;
        #pragma unroll
        for (int kk = 0; kk < BK / 16; kk++) {
            const int byteCol = kk * 32 + ((lane >> 4) << 4);
            uint32_t ah[2][4];
            #pragma unroll
            for (int mi = 0; mi < 2; mi++) {
                int row = wm * 32 + mi * 16 + (lane & 15);
                uint32_t so = (uint32_t)(row * 128 + byteCol) ^ ((uint32_t)(row & 7) << 4);
                ldsm4(ah[mi], st + T_A + so);
            }
            #pragma unroll
            for (int nt = 0; nt < 4; nt++) {
                int row = wn * 64 + nt * 16 + (lane & 15);
                uint32_t so = (uint32_t)(row * 128 + byteCol) ^ ((uint32_t)(row & 7) << 4);
                uint32_t rh[4];
                ldsm4(rh, st + T_B + so);
                uint32_t b0[2] = { rh[0], rh[2] }, b1[2] = { rh[1], rh[3] };
                #pragma unroll
                for (int mi = 0; mi < 2; mi++) {
                    mma_f16(acc[mi][2*nt+0], ah[mi], b0);
                    mma_f16(acc[mi][2*nt+1], ah[mi], b1);
                }
            }
        }
        buf = (buf == NSTAGE - 1) ? 0 : buf + 1;
        pbuf = (pbuf == NSTAGE - 1) ? 0 : pbuf + 1;
    }

    // ---------------- epilogue ----------------
    const int qrow = lane >> 2;        // 0..7
    const int qcol = (lane & 3) * 2;   // 0,2,4,6 (always even)
    #pragma unroll
    for (int mi = 0; mi < 2; mi++) {
        #pragma unroll
        for (int ni = 0; ni < 8; ni++) {
            const int n0 = bn + wn * 64 + ni * 8 + qcol;
            float bias0, bias1;
            if (MODE == 2) {
                const int f = n0 >> 1;
                bias0 = bias[f];       // b_z
                bias1 = bias2[f];      // b_h
            } else {
                bias0 = bias[n0];
                bias1 = bias[n0 + 1];
            }
            #pragma unroll
            for (int half_ = 0; half_ < 2; half_++) {
                const int m = bm + wm * 32 + mi * 16 + qrow + half_ * 8;
                float v0 = acc[mi][ni][half_ * 2 + 0] + bias0;
                float v1 = acc[mi][ni][half_ * 2 + 1] + bias1;
                if (MODE == 1) {
                    v0 *= 1.f / (1.f + __expf(-v0));
                    v1 *= 1.f / (1.f + __expf(-v1));
                } else if (MODE == 2) {
                    v0 = 1.f / (1.f + __expf(-v0));   // z = sigmoid ; v1 = ht (no act)
                }
                if (MODE == 0) {
                    *(float2*)&Cf[(size_t)m * N + n0] = make_float2(v0, v1);
                } else {
                    __half h0 = __float2half_rn(v0);
                    __half h1 = __float2half_rn(v1);
                    uint32_t hp = (uint32_t)__half_as_ushort(h0) | ((uint32_t)__half_as_ushort(h1) << 16);
                    *(uint32_t*)&Ch[(size_t)m * N + n0] = hp;
                }
            }
        }
    }
}

// ---------------- weight transpose: W[K,N] fp32 -> T[(n*mult+off), K] fp16 ----------
__global__ __launch_bounds__(256)
void transpose_h(const float* __restrict__ W, __half* __restrict__ T, int K, int N,
                 int mult, int off)
{
    __shared__ float t[32][33];
    const int n0 = blockIdx.x * 32, k0 = blockIdx.y * 32;
    const int tx = threadIdx.x & 31, ty0 = threadIdx.x >> 5;
    #pragma unroll
    for (int dy = 0; dy < 32; dy += 8)
        t[ty0 + dy][tx] = W[(size_t)(k0 + ty0 + dy) * N + n0 + tx];
    __syncthreads();
    #pragma unroll
    for (int dy = 0; dy < 32; dy += 8) {
        int ty = ty0 + dy;
        T[(size_t)((n0 + ty) * mult + off) * K + k0 + tx] = __float2half_rn(t[tx][ty]);
    }
}

// ---------------- x convert: fp32 -> fp16 ----------------
__global__ __launch_bounds__(256)
void convert_h(const float* __restrict__ x, __half* __restrict__ h, int n)
{
    int i = blockIdx.x * blockDim.x + threadIdx.x;
    if (i < n) h[i] = __float2half_rn(x[i]);
}

// ---------------- scan (minGRU), 3-pass chunked, 2 features/thread ----------
// zht interleaved (z, ht); two adjacent features = 8 bytes = one float2 load.
__global__ __launch_bounds__(256)
void scan_pass1(const __half* __restrict__ zht,
                float* __restrict__ aggA, float* __restrict__ aggB, int bb0)
{
    int t = blockIdx.x * blockDim.x + threadIdx.x;      // over 2 batches, EXPD/2 pairs
    int fp = t % (EXPD / 2), rc = t / (EXPD / 2);
    int c = rc % NCH, bb = bb0 + rc / NCH;
    int f = fp * 2;
    size_t base = ((size_t)bb * SEQ + (size_t)c * CHL) * (2 * EXPD) + 2 * f;
    float A0 = 1.f, B0 = 0.f, A1 = 1.f, B1 = 0.f;
    #pragma unroll 4
    for (int i = 0; i < CHL; i++) {
        uint2 pv = *(const uint2*)(zht + base + (size_t)i * (2 * EXPD));
        __half2 p0 = *(__half2*)&pv.x, p1 = *(__half2*)&pv.y;
        float z0 = __half2float(__low2half(p0)), h0 = __half2float(__high2half(p0));
        float z1 = __half2float(__low2half(p1)), h1 = __half2float(__high2half(p1));
        A0 = A0 * (1.f - z0); B0 = B0 * (1.f - z0) + z0 * h0;
        A1 = A1 * (1.f - z1); B1 = B1 * (1.f - z1) + z1 * h1;
    }
    size_t tg = ((size_t)bb * NCH + c) * EXPD + f;
    *(float2*)&aggA[tg] = make_float2(A0, A1);
    *(float2*)&aggB[tg] = make_float2(B0, B1);
}

__global__ __launch_bounds__(256)
void scan_pass2(const float* __restrict__ aggA, const float* __restrict__ aggB,
                float* __restrict__ carry, int bb0)
{
    int t = blockIdx.x * blockDim.x + threadIdx.x;      // over 2 batches, EXPD/2 pairs
    int fp = t % (EXPD / 2), bb = bb0 + t / (EXPD / 2);
    int f = fp * 2;
    size_t base = (size_t)bb * NCH * EXPD + f;
    float h0 = 0.f, h1 = 0.f;
    for (int c = 0; c < NCH; c++) {
        size_t idx = base + (size_t)c * EXPD;
        *(float2*)&carry[idx] = make_float2(h0, h1);
        float2 a = *(const float2*)&aggA[idx];
        float2 b = *(const float2*)&aggB[idx];
        h0 = a.x * h0 + b.x;
        h1 = a.y * h1 + b.y;
    }
}

__global__ __launch_bounds__(256)
void scan_pass3(const __half* __restrict__ zht,
                const float* __restrict__ carry, const __half* __restrict__ xskip,
                __half* __restrict__ u, int bb0)
{
    int t = blockIdx.x * blockDim.x + threadIdx.x;      // over 2 batches, EXPD/2 pairs
    int fp = t % (EXPD / 2), rc = t / (EXPD / 2);
    int c = rc % NCH, bb = bb0 + rc / NCH;
    int f = fp * 2;
    size_t row0 = (size_t)bb * SEQ + (size_t)c * CHL;
    size_t basez = row0 * (2 * EXPD) + 2 * f;
    size_t baseu = row0 * EXPD + f;
    float2 cv = *(const float2*)&carry[((size_t)bb * NCH + c) * EXPD + f];
    float h0 = cv.x, h1 = cv.y;
    #pragma unroll 4
    for (int i = 0; i < CHL; i++) {
        uint2 pv = *(const uint2*)(zht + basez + (size_t)i * (2 * EXPD));
        __half2 p0 = *(__half2*)&pv.x, p1 = *(__half2*)&pv.y;
        float z0 = __half2float(__low2half(p0)), ht0 = __half2float(__high2half(p0));
        float z1 = __half2float(__low2half(p1)), ht1 = __half2float(__high2half(p1));
        h0 = (1.f - z0) * h0 + z0 * ht0;
        h1 = (1.f - z1) * h1 + z1 * ht1;
        size_t iu = baseu + (size_t)i * EXPD;
        __half2 xs = *(const __half2*)&xskip[iu];
        __half u0 = __float2half_rn(__half2float(__low2half(xs)) + h0);
        __half u1 = __float2half_rn(__half2float(__high2half(xs)) + h1);
        *(uint32_t*)&u[iu] = (uint32_t)__half_as_ushort(u0) | ((uint32_t)__half_as_ushort(u1) << 16);
    }
}

// ---------------- launch (R15 schedule; graph-capturable) ----------------
extern "C" void kernel_launch(void* const* d_in, const int* in_sizes, int n_in,
                              void* d_out, int out_size)
{
    const float* x     = (const float*)d_in[0];
    const float* W_in1 = (const float*)d_in[1];
    const float* b_in1 = (const float*)d_in[2];
    const float* W_in2 = (const float*)d_in[3];
    const float* b_in2 = (const float*)d_in[4];
    const float* W_z   = (const float*)d_in[5];
    const float* b_z   = (const float*)d_in[6];
    const float* W_h   = (const float*)d_in[7];
    const float* b_h   = (const float*)d_in[8];
    const float* W_out = (const float*)d_in[9];
    const float* b_out = (const float*)d_in[10];
    float* out = (float*)d_out;

    __half *xh, *w1h, *w2h, *wzh, *woh, *xin, *zht, *xskip, *u;
    float *aggA, *aggB, *carry;
    cudaGetSymbolAddress((void**)&xh, g_xh);
    cudaGetSymbolAddress((void**)&w1h, g_w1h);   cudaGetSymbolAddress((void**)&w2h, g_w2h);
    cudaGetSymbolAddress((void**)&wzh, g_wzh);   cudaGetSymbolAddress((void**)&woh, g_woh);
    cudaGetSymbolAddress((void**)&xin, g_xin);
    cudaGetSymbolAddress((void**)&zht, g_zht);
    cudaGetSymbolAddress((void**)&xskip, g_xskip);
    cudaGetSymbolAddress((void**)&u, g_u);
    cudaGetSymbolAddress((void**)&aggA, g_aggA); cudaGetSymbolAddress((void**)&aggB, g_aggB);
    cudaGetSymbolAddress((void**)&carry, g_carry);

    cudaFuncSetAttribute(gemm_mma<0>, cudaFuncAttributeMaxDynamicSharedMemorySize, SMEM_BYTES);
    cudaFuncSetAttribute(gemm_mma<1>, cudaFuncAttributeMaxDynamicSharedMemorySize, SMEM_BYTES);
    cudaFuncSetAttribute(gemm_mma<2>, cudaFuncAttributeMaxDynamicSharedMemorySize, SMEM_BYTES);

    static cudaStream_t s1 = nullptr, s2 = nullptr;
    static cudaEvent_t ev_root, ev_conv, ev_w1, ev_wzh, ev_in1c1, ev_in2, ev_wo,
                       ev_gate0, ev_out0;
    if (!s1) {
        cudaStreamCreateWithFlags(&s1, cudaStreamNonBlocking);
        cudaStreamCreateWithFlags(&s2, cudaStreamNonBlocking);
        cudaEventCreateWithFlags(&ev_root,  cudaEventDisableTiming);
        cudaEventCreateWithFlags(&ev_conv,  cudaEventDisableTiming);
        cudaEventCreateWithFlags(&ev_w1,    cudaEventDisableTiming);
        cudaEventCreateWithFlags(&ev_wzh,   cudaEventDisableTiming);
        cudaEventCreateWithFlags(&ev_in1c1, cudaEventDisableTiming);
        cudaEventCreateWithFlags(&ev_in2,   cudaEventDisableTiming);
        cudaEventCreateWithFlags(&ev_wo,    cudaEventDisableTiming);
        cudaEventCreateWithFlags(&ev_gate0, cudaEventDisableTiming);
        cudaEventCreateWithFlags(&ev_out0,  cudaEventDisableTiming);
    }
    cudaStream_t s0 = 0;   // legacy/capture stream

    cudaEventRecord(ev_root, s0);
    cudaStreamWaitEvent(s1, ev_root, 0);
    cudaStreamWaitEvent(s2, ev_root, 0);

    // s1: W_in1^T, interleaved W_z/W_h transpose
    transpose_h<<<dim3(EXPD/32, HID/32), 256, 0, s1>>>(W_in1, w1h, HID, EXPD, 1, 0);
    cudaEventRecord(ev_w1, s1);
    transpose_h<<<dim3(EXPD/32, EXPD/32), 256, 0, s1>>>(W_z, wzh, EXPD, EXPD, 2, 0);
    transpose_h<<<dim3(EXPD/32, EXPD/32), 256, 0, s1>>>(W_h, wzh, EXPD, EXPD, 2, 1);
    cudaEventRecord(ev_wzh, s1);

    // s2: W_in2^T, W_out^T
    transpose_h<<<dim3(EXPD/32, HID/32), 256, 0, s2>>>(W_in2, w2h, HID, EXPD, 1, 0);
    transpose_h<<<dim3(HID/32, EXPD/32), 256, 0, s2>>>(W_out, woh, EXPD, HID, 1, 0);
    cudaEventRecord(ev_wo, s2);

    // s0: convert x, in1 on half0
    convert_h<<<(M_TOT * HID + 255) / 256, 256, 0, s0>>>(x, xh, M_TOT * HID);
    cudaEventRecord(ev_conv, s0);
    cudaStreamWaitEvent(s0, ev_w1, 0);
    gemm_mma<1><<<dim3(EXPD/BN, HM/BM), NTHREADS, SMEM_BYTES, s0>>>(
        xh, w1h, b_in1, nullptr, nullptr, xin, HM, EXPD, HID);

    // s1: in1 on half1 (after wzh transposes; needs xh)
    cudaStreamWaitEvent(s1, ev_conv, 0);
    gemm_mma<1><<<dim3(EXPD/BN, HM/BM), NTHREADS, SMEM_BYTES, s1>>>(
        xh + (size_t)HM * HID, w1h, b_in1, nullptr, nullptr,
        xin + (size_t)HM * EXPD, HM, EXPD, HID);
    cudaEventRecord(ev_in1c1, s1);

    // s2: in2 GEMM (full M; needs xh)
    cudaStreamWaitEvent(s2, ev_conv, 0);
    gemm_mma<1><<<dim3(EXPD/BN, M_TOT/BM), NTHREADS, SMEM_BYTES, s2>>>(
        xh, w2h, b_in2, nullptr, nullptr, xskip, M_TOT, EXPD, HID);
    cudaEventRecord(ev_in2, s2);

    // s0: gate half0, then gate half1
    cudaStreamWaitEvent(s0, ev_wzh, 0);
    gemm_mma<2><<<dim3(2*EXPD/BN, HM/BM), NTHREADS, SMEM_BYTES, s0>>>(
        xin, wzh, b_z, b_h, nullptr, zht, HM, 2*EXPD, EXPD);
    cudaEventRecord(ev_gate0, s0);
    cudaStreamWaitEvent(s0, ev_in1c1, 0);
    gemm_mma<2><<<dim3(2*EXPD/BN, HM/BM), NTHREADS, SMEM_BYTES, s0>>>(
        xin + (size_t)HM * EXPD, wzh, b_z, b_h, nullptr,
        zht + (size_t)HM * 2 * EXPD, HM, 2*EXPD, EXPD);

    // s2: scan + out for batches 0-1 (overlaps gate half1 on s0)
    const int p1v = NCH * EXPD;          // threads per 2 batches (2 features/thread)
    cudaStreamWaitEvent(s2, ev_gate0, 0);
    scan_pass1<<<p1v / 256, 256, 0, s2>>>(zht, aggA, aggB, 0);
    scan_pass2<<<EXPD / 256, 256, 0, s2>>>(aggA, aggB, carry, 0);
    scan_pass3<<<p1v / 256, 256, 0, s2>>>(zht, carry, xskip, u, 0);   // xskip ready (s2 in-order after in2)
    gemm_mma<0><<<dim3(HID/BN, HM/BM), NTHREADS, SMEM_BYTES, s2>>>(
        u, woh, b_out, nullptr, out, nullptr, HM, HID, EXPD);
    cudaEventRecord(ev_out0, s2);

    // s0: scan + out for batches 2-3 (out half0 on s2 overlaps this scan)
    scan_pass1<<<p1v / 256, 256, 0, s0>>>(zht, aggA, aggB, 2);
    scan_pass2<<<EXPD / 256, 256, 0, s0>>>(aggA, aggB, carry, 2);
    cudaStreamWaitEvent(s0, ev_in2, 0);
    scan_pass3<<<p1v / 256, 256, 0, s0>>>(zht, carry, xskip, u, 2);
    cudaStreamWaitEvent(s0, ev_wo, 0);
    gemm_mma<0><<<dim3(HID/BN, HM/BM), NTHREADS, SMEM_BYTES, s0>>>(
        u + (size_t)HM * EXPD, woh, b_out, nullptr,
        out + (size_t)HM * HID, nullptr, HM, HID, EXPD);

    // join side streams back into capture stream
    cudaStreamWaitEvent(s0, ev_out0, 0);
}